// round 16
// baseline (speedup 1.0000x reference)
#include <cuda_runtime.h>
#include <math.h>
#include <float.h>

// Problem constants (fixed shapes)
#define V_   8000
#define D_   300
#define B_   128
#define L_   300
#define NG   3             // NGRAM
#define KW   (2*NG+1)      // 7 window taps
#define WP   8             // padded tap row: w0..w6, eta
#define C_   54
#define DC   32            // D-chunk width
#define NCHUNK ((D_ + DC - 1) / DC)   // 10
#define NSEG 20            // row segments per block
#define SEGL (L_ / NSEG)   // 15
#define NTHR (16 * NSEG)   // 320 threads (16 float2-lanes x 20 segs)
#define HR   (L_ + 8)      // padded h rows: 3 halo top, 5 halo bottom

// Scratch (device globals; no allocations allowed)
__device__ __align__(16) float g_w[B_ * L_ * WP];  // per-doc [w0..w6, eta] rows
__device__ float g_x[B_ * D_];        // relu(pooled)

// ---------------------------------------------------------------------------
// Kernel 0: gather edge weights + eta into padded rows.
// invalid taps get w=1.0 (pairs with -FLT_MAX halo in mp); slot 7 = eta.
// grid (B, 2): two blocks per doc for extra memory-level parallelism.
// eid index fits int32 (8000*8000 = 64M).
// ---------------------------------------------------------------------------
__global__ void edgew_kernel(const int* __restrict__ docs,
                             const int* __restrict__ edges_matrix,
                             const float* __restrict__ edge_w,
                             const float* __restrict__ node_eta) {
    __shared__ int tokS[L_];
    int b = blockIdx.x;
    int half = blockIdx.y;              // 0 or 1
    for (int l = threadIdx.x; l < L_; l += blockDim.x)
        tokS[l] = docs[b * L_ + l];
    __syncthreads();
    const int total = L_ * WP;          // 2400
    const int i0 = half * (total / 2);
    const int i1 = i0 + total / 2;
    for (int i = i0 + threadIdx.x; i < i1; i += blockDim.x) {
        int l = i >> 3, k = i & 7;
        float v;
        if (k == 7) {
            v = node_eta[tokS[l]];
        } else {
            int nbr = l - NG + k;
            if (nbr < 0 || nbr >= L_) {
                v = 1.0f;
            } else {
                int eid = edges_matrix[tokS[l] * V_ + tokS[nbr]];
                v = edge_w[eid];
            }
        }
        g_w[b * (L_ * WP) + i] = v;
    }
}

// ---------------------------------------------------------------------------
// Kernel 1: 2-step message passing, one (doc, 32-wide D-chunk) per block.
// Step 1: in-place h update (read ptr 4 rows ahead of write ptr in-segment;
// boundary rows preloaded to regs before barrier).
// Step 2: no smem writes, pool accumulated in registers.
// smem 50.2 KB -> 4 blocks/SM (40 warps/SM).
// ---------------------------------------------------------------------------
__global__ void __launch_bounds__(NTHR, 4)
mp_kernel(const float* __restrict__ node_embed,
          const int* __restrict__ docs) {
    extern __shared__ float sm[];
    float* hS  = sm;                    // HR*32 = 9856 floats
    float* wS  = hS + HR * DC;          // 2400 floats (16B aligned)
    int*  tokS = (int*)(wS + L_ * WP);  // 300 ints

    const int b  = blockIdx.y;
    const int d0 = blockIdx.x * DC;
    const int Dc = (D_ - d0) < DC ? (D_ - d0) : DC;   // 32 or 12
    const int tid = threadIdx.x;

    // tokens + packed w/eta rows (float4) + halo rows
    for (int l = tid; l < L_; l += NTHR)
        tokS[l] = docs[b * L_ + l];
    {
        const float4* gw4 = (const float4*)&g_w[b * (L_ * WP)];
        float4* wS4 = (float4*)wS;
        for (int i = tid; i < (L_ * WP) / 4; i += NTHR)
            wS4[i] = gw4[i];
    }
    for (int i = tid; i < 3 * DC; i += NTHR) hS[i] = -FLT_MAX;
    for (int i = tid; i < 5 * DC; i += NTHR) hS[303 * DC + i] = -FLT_MAX;
    __syncthreads();

    // h init: padded row l+3 holds h(l); float4 (8 lanes/row); pad cols with 0
    for (int i = tid; i < L_ * (DC / 4); i += NTHR) {
        int l = i >> 3, dq = (i & 7) * 4;
        float4 v = make_float4(0.f, 0.f, 0.f, 0.f);
        if (dq < Dc)
            v = *(const float4*)&node_embed[(long long)tokS[l] * D_ + d0 + dq];
        *(float4*)&hS[(3 + l) * DC + dq] = v;
    }
    __syncthreads();

    // Thread owns column pair dp within rows [ls, ls+SEGL)
    const int dp  = (tid & 15) * 2;
    const int seg = tid >> 4;           // 0..19
    const int ls  = seg * SEGL;
    const int le  = ls + SEGL;

    // ---------------- Step 1: in-place update of hS ----------------
    {
        // Preload (old values): window rows padded ls..ls+6 = h_old(ls-3..ls+3)
        float2 w0 = *(float2*)&hS[(ls + 0) * DC + dp];
        float2 w1 = *(float2*)&hS[(ls + 1) * DC + dp];
        float2 w2 = *(float2*)&hS[(ls + 2) * DC + dp];
        float2 w3 = *(float2*)&hS[(ls + 3) * DC + dp];
        float2 w4 = *(float2*)&hS[(ls + 4) * DC + dp];
        float2 w5 = *(float2*)&hS[(ls + 5) * DC + dp];
        float2 w6 = *(float2*)&hS[(ls + 6) * DC + dp];
        // tail rows padded le+3..le+5 = h_old(le..le+2) (cross-segment)
        float2 t0 = *(float2*)&hS[(le + 3) * DC + dp];
        float2 t1 = *(float2*)&hS[(le + 4) * DC + dp];
        float2 t2 = *(float2*)&hS[(le + 5) * DC + dp];
        // first w row
        float4 wa = *(const float4*)&wS[ls * WP];
        float4 wb = *(const float4*)&wS[ls * WP + 4];
        __syncthreads();   // all preloads done before any in-place write

        #pragma unroll
        for (int j = 0; j < SEGL; j++) {
            int l = ls + j;
            float4 ca = wa, cb = wb;
            if (j + 1 < SEGL) {                       // prefetch next w row
                wa = *(const float4*)&wS[(l + 1) * WP];
                wb = *(const float4*)&wS[(l + 1) * WP + 4];
            }
            float mx = fmaxf(fmaxf(fmaxf(ca.x * w0.x, ca.y * w1.x),
                                   fmaxf(ca.z * w2.x, ca.w * w3.x)),
                             fmaxf(fmaxf(cb.x * w4.x, cb.y * w5.x), cb.z * w6.x));
            float my = fmaxf(fmaxf(fmaxf(ca.x * w0.y, ca.y * w1.y),
                                   fmaxf(ca.z * w2.y, ca.w * w3.y)),
                             fmaxf(fmaxf(cb.x * w4.y, cb.y * w5.y), cb.z * w6.y));
            // eta*h + (1-eta)*m == m + eta*(h - m)
            float2 o;
            o.x = fmaf(cb.w, w3.x - mx, mx);
            o.y = fmaf(cb.w, w3.y - my, my);
            *(float2*)&hS[(l + 3) * DC + dp] = o;     // in-place write h(l)
            // shift window; next w6 = h_old(l+4) = padded row l+7
            w0 = w1; w1 = w2; w2 = w3; w3 = w4; w4 = w5; w5 = w6;
            if (j + 1 < SEGL) {
                if (j < SEGL - 4)
                    w6 = *(float2*)&hS[(l + 7) * DC + dp];  // own-segment row, safe
                else if (j == SEGL - 4) w6 = t0;
                else if (j == SEGL - 3) w6 = t1;
                else                    w6 = t2;            // j == SEGL - 2
            }
        }
        __syncthreads();   // step-1 writes complete before step-2 reads
    }

    // ------- Step 2: NO smem writes; pool sum accumulated in registers -----
    float2 s = make_float2(0.f, 0.f);
    {
        float2 w0 = *(float2*)&hS[(ls + 0) * DC + dp];
        float2 w1 = *(float2*)&hS[(ls + 1) * DC + dp];
        float2 w2 = *(float2*)&hS[(ls + 2) * DC + dp];
        float2 w3 = *(float2*)&hS[(ls + 3) * DC + dp];
        float2 w4 = *(float2*)&hS[(ls + 4) * DC + dp];
        float2 w5 = *(float2*)&hS[(ls + 5) * DC + dp];
        float2 w6 = *(float2*)&hS[(ls + 6) * DC + dp];
        float4 wa = *(const float4*)&wS[ls * WP];
        float4 wb = *(const float4*)&wS[ls * WP + 4];

        #pragma unroll
        for (int j = 0; j < SEGL; j++) {
            int l = ls + j;
            float4 ca = wa, cb = wb;
            if (j + 1 < SEGL) {
                wa = *(const float4*)&wS[(l + 1) * WP];
                wb = *(const float4*)&wS[(l + 1) * WP + 4];
            }
            float mx = fmaxf(fmaxf(fmaxf(ca.x * w0.x, ca.y * w1.x),
                                   fmaxf(ca.z * w2.x, ca.w * w3.x)),
                             fmaxf(fmaxf(cb.x * w4.x, cb.y * w5.x), cb.z * w6.x));
            float my = fmaxf(fmaxf(fmaxf(ca.x * w0.y, ca.y * w1.y),
                                   fmaxf(ca.z * w2.y, ca.w * w3.y)),
                             fmaxf(fmaxf(cb.x * w4.y, cb.y * w5.y), cb.z * w6.y));
            s.x += fmaf(cb.w, w3.x - mx, mx);       // h2(l) accumulated directly
            s.y += fmaf(cb.w, w3.y - my, my);
            // shift window; reads are always safe (no writes this step)
            w0 = w1; w1 = w2; w2 = w3; w3 = w4; w4 = w5; w5 = w6;
            if (j + 1 < SEGL)
                w6 = *(float2*)&hS[(l + 7) * DC + dp];
        }
    }

    // partial sums via wS scratch (barrier first: others may still read wS)
    __syncthreads();
    *(float2*)&wS[seg * DC + dp] = s;    // NSEG*DC = 640 <= 2400
    __syncthreads();
    if (seg == 0 && dp < Dc) {
        float tx = 0.f, ty = 0.f;
        #pragma unroll
        for (int p = 0; p < NSEG; p++) {
            float2 v = *(float2*)&wS[p * DC + dp];
            tx += v.x; ty += v.y;
        }
        g_x[b * D_ + d0 + dp]     = fmaxf(tx, 0.f);
        g_x[b * D_ + d0 + dp + 1] = fmaxf(ty, 0.f);
    }
}

// ---------------------------------------------------------------------------
// Kernel 2 (fused BN + GEMM + sigmoid): one block per batch row, 432 threads.
// Phase 1: threads 0..299 each own feature d — coalesced column sum + sumsq
// over the 128 batch rows (redundant per block, but ~0.6us), normalize into
// xs. Phase 2: 54 outputs x 8 d-partitions, direct LDG of W (L2-resident),
// 8 independent accumulators, clamped W index (xs zero-padded).
// ---------------------------------------------------------------------------
__global__ void out_kernel(const float* __restrict__ W,
                           const float* __restrict__ bias,
                           const float* __restrict__ gamma,
                           const float* __restrict__ beta,
                           float* __restrict__ out) {
    __shared__ float xs[304];
    __shared__ float red[8][C_];
    int b = blockIdx.x;
    int tid = threadIdx.x;

    // Phase 1: BN stats for feature tid (tid < 300), normalize own-b value.
    if (tid < 304) {
        float nv = 0.f;
        if (tid < D_) {
            int d = tid;
            float a0 = 0.f, a1 = 0.f, q0 = 0.f, q1 = 0.f;
            #pragma unroll 4
            for (int b2 = 0; b2 < B_; b2 += 2) {
                float v0 = g_x[b2 * D_ + d];
                float v1 = g_x[(b2 + 1) * D_ + d];
                a0 += v0; a1 += v1;
                q0 = fmaf(v0, v0, q0); q1 = fmaf(v1, v1, q1);
            }
            float mean = (a0 + a1) * (1.f / B_);
            float var  = (q0 + q1) * (1.f / B_) - mean * mean;
            float sc = gamma[d] * rsqrtf(var + 1e-5f);
            nv = (g_x[b * D_ + d] - mean) * sc + beta[d];
        }
        xs[tid] = nv;   // tid in [300,304) -> 0 padding
    }
    __syncthreads();

    // Phase 2: GEMM row + sigmoid
    int c = tid % C_, part = tid / C_;  // part 0..7
    float acc[8] = {0.f, 0.f, 0.f, 0.f, 0.f, 0.f, 0.f, 0.f};
    #pragma unroll
    for (int j = 0; j < 38; j++) {
        int dd = part + 8 * j;                 // <= 303
        int wi = dd < D_ ? dd : D_ - 1;        // clamp; xs[dd]=0 kills product
        acc[j & 7] = fmaf(xs[dd], __ldg(&W[wi * C_ + c]), acc[j & 7]);
    }
    red[part][c] = ((acc[0] + acc[1]) + (acc[2] + acc[3]))
                 + ((acc[4] + acc[5]) + (acc[6] + acc[7]));
    __syncthreads();
    if (part == 0) {
        float tot = bias[c];
        #pragma unroll
        for (int p = 0; p < 8; p++) tot += red[p][c];
        out[b * C_ + c] = 1.f / (1.f + expf(-tot));
    }
}

// ---------------------------------------------------------------------------
extern "C" void kernel_launch(void* const* d_in, const int* in_sizes, int n_in,
                              void* d_out, int out_size) {
    const float* node_embed   = (const float*)d_in[0];
    const float* node_eta     = (const float*)d_in[1];
    const float* edge_w       = (const float*)d_in[2];
    const float* bn_gamma     = (const float*)d_in[3];
    const float* bn_beta      = (const float*)d_in[4];
    const float* Wmat         = (const float*)d_in[5];
    const float* bias         = (const float*)d_in[6];
    const int*   docs         = (const int*)d_in[7];
    const int*   edges_matrix = (const int*)d_in[8];
    float* out = (float*)d_out;

    const int mpSmem = (HR * DC + L_ * WP) * (int)sizeof(float)
                     + L_ * (int)sizeof(int);   // 50,224 B
    cudaFuncSetAttribute(mp_kernel, cudaFuncAttributeMaxDynamicSharedMemorySize, mpSmem);

    dim3 egrid(B_, 2);
    edgew_kernel<<<egrid, 512>>>(docs, edges_matrix, edge_w, node_eta);

    dim3 grid(NCHUNK, B_);
    mp_kernel<<<grid, NTHR, mpSmem>>>(node_embed, docs);

    out_kernel<<<B_, 8 * C_>>>(Wmat, bias, bn_gamma, bn_beta, out);

    (void)in_sizes; (void)n_in; (void)out_size;
}

// round 17
// speedup vs baseline: 1.1750x; 1.1750x over previous
#include <cuda_runtime.h>
#include <math.h>
#include <float.h>

// Problem constants (fixed shapes)
#define V_   8000
#define D_   300
#define B_   128
#define L_   300
#define NG   3             // NGRAM
#define KW   (2*NG+1)      // 7 window taps
#define WP   8             // padded tap row: w0..w6, eta
#define C_   54
#define DC   32            // D-chunk width
#define NCHUNK ((D_ + DC - 1) / DC)   // 10
#define NSEG 20            // row segments per block
#define SEGL (L_ / NSEG)   // 15
#define NTHR (16 * NSEG)   // 320 threads (16 float2-lanes x 20 segs)
#define HR   (L_ + 8)      // padded h rows: 3 halo top, 5 halo bottom

// Scratch (device globals; no allocations allowed)
__device__ __align__(16) float g_w[B_ * L_ * WP];  // per-doc [w0..w6, eta] rows
__device__ float g_x[B_ * D_];        // relu(pooled)
__device__ float g_s[D_];             // BN scale
__device__ float g_t[D_];             // BN shift

// ---------------------------------------------------------------------------
// Kernel 0: gather edge weights + eta. ONE THREAD PER ITEM (307200 threads,
// 64 warps/SM) -> max MLP against the eid->w DRAM-dependent chain.
// invalid taps get w=1.0 (pairs with -FLT_MAX halo in mp); slot 7 = eta.
// ---------------------------------------------------------------------------
__global__ void __launch_bounds__(512)
edgew_kernel(const int* __restrict__ docs,
             const int* __restrict__ edges_matrix,
             const float* __restrict__ edge_w,
             const float* __restrict__ node_eta) {
    int i = blockIdx.x * 512 + threadIdx.x;     // 0..307199
    int b = i / (L_ * WP);
    int r = i - b * (L_ * WP);
    int l = r >> 3, k = r & 7;
    const int* drow = docs + b * L_;            // L2/L1-hot (150 KB total)
    int tok = __ldg(&drow[l]);
    float v;
    if (k == 7) {
        v = __ldg(&node_eta[tok]);
    } else {
        int nbr = l - NG + k;
        if (nbr < 0 || nbr >= L_) {
            v = 1.0f;
        } else {
            int tn  = __ldg(&drow[nbr]);
            int eid = __ldg(&edges_matrix[tok * V_ + tn]);   // random DRAM
            v = __ldg(&edge_w[eid]);                         // random DRAM/L2
        }
    }
    g_w[i] = v;
}

// ---------------------------------------------------------------------------
// Kernel 1: 2-step message passing, one (doc, 32-wide D-chunk) per block.
// Step 1: in-place h update (read ptr 4 rows ahead of write ptr in-segment;
// boundary rows preloaded to regs before barrier).
// Step 2: no smem writes, pool accumulated in registers.
// smem 50.2 KB -> 4 blocks/SM (40 warps/SM).
// ---------------------------------------------------------------------------
__global__ void __launch_bounds__(NTHR, 4)
mp_kernel(const float* __restrict__ node_embed,
          const int* __restrict__ docs) {
    extern __shared__ float sm[];
    float* hS  = sm;                    // HR*32 = 9856 floats
    float* wS  = hS + HR * DC;          // 2400 floats (16B aligned)
    int*  tokS = (int*)(wS + L_ * WP);  // 300 ints

    const int b  = blockIdx.y;
    const int d0 = blockIdx.x * DC;
    const int Dc = (D_ - d0) < DC ? (D_ - d0) : DC;   // 32 or 12
    const int tid = threadIdx.x;

    // tokens + packed w/eta rows (float4) + halo rows
    for (int l = tid; l < L_; l += NTHR)
        tokS[l] = docs[b * L_ + l];
    {
        const float4* gw4 = (const float4*)&g_w[b * (L_ * WP)];
        float4* wS4 = (float4*)wS;
        for (int i = tid; i < (L_ * WP) / 4; i += NTHR)
            wS4[i] = gw4[i];
    }
    for (int i = tid; i < 3 * DC; i += NTHR) hS[i] = -FLT_MAX;
    for (int i = tid; i < 5 * DC; i += NTHR) hS[303 * DC + i] = -FLT_MAX;
    __syncthreads();

    // h init: padded row l+3 holds h(l); float4 (8 lanes/row); pad cols with 0
    for (int i = tid; i < L_ * (DC / 4); i += NTHR) {
        int l = i >> 3, dq = (i & 7) * 4;
        float4 v = make_float4(0.f, 0.f, 0.f, 0.f);
        if (dq < Dc)
            v = *(const float4*)&node_embed[(long long)tokS[l] * D_ + d0 + dq];
        *(float4*)&hS[(3 + l) * DC + dq] = v;
    }
    __syncthreads();

    // Thread owns column pair dp within rows [ls, ls+SEGL)
    const int dp  = (tid & 15) * 2;
    const int seg = tid >> 4;           // 0..19
    const int ls  = seg * SEGL;
    const int le  = ls + SEGL;

    // ---------------- Step 1: in-place update of hS ----------------
    {
        // Preload (old values): window rows padded ls..ls+6 = h_old(ls-3..ls+3)
        float2 w0 = *(float2*)&hS[(ls + 0) * DC + dp];
        float2 w1 = *(float2*)&hS[(ls + 1) * DC + dp];
        float2 w2 = *(float2*)&hS[(ls + 2) * DC + dp];
        float2 w3 = *(float2*)&hS[(ls + 3) * DC + dp];
        float2 w4 = *(float2*)&hS[(ls + 4) * DC + dp];
        float2 w5 = *(float2*)&hS[(ls + 5) * DC + dp];
        float2 w6 = *(float2*)&hS[(ls + 6) * DC + dp];
        // tail rows padded le+3..le+5 = h_old(le..le+2) (cross-segment)
        float2 t0 = *(float2*)&hS[(le + 3) * DC + dp];
        float2 t1 = *(float2*)&hS[(le + 4) * DC + dp];
        float2 t2 = *(float2*)&hS[(le + 5) * DC + dp];
        // first w row
        float4 wa = *(const float4*)&wS[ls * WP];
        float4 wb = *(const float4*)&wS[ls * WP + 4];
        __syncthreads();   // all preloads done before any in-place write

        #pragma unroll
        for (int j = 0; j < SEGL; j++) {
            int l = ls + j;
            float4 ca = wa, cb = wb;
            if (j + 1 < SEGL) {                       // prefetch next w row
                wa = *(const float4*)&wS[(l + 1) * WP];
                wb = *(const float4*)&wS[(l + 1) * WP + 4];
            }
            float mx = fmaxf(fmaxf(fmaxf(ca.x * w0.x, ca.y * w1.x),
                                   fmaxf(ca.z * w2.x, ca.w * w3.x)),
                             fmaxf(fmaxf(cb.x * w4.x, cb.y * w5.x), cb.z * w6.x));
            float my = fmaxf(fmaxf(fmaxf(ca.x * w0.y, ca.y * w1.y),
                                   fmaxf(ca.z * w2.y, ca.w * w3.y)),
                             fmaxf(fmaxf(cb.x * w4.y, cb.y * w5.y), cb.z * w6.y));
            // eta*h + (1-eta)*m == m + eta*(h - m)
            float2 o;
            o.x = fmaf(cb.w, w3.x - mx, mx);
            o.y = fmaf(cb.w, w3.y - my, my);
            *(float2*)&hS[(l + 3) * DC + dp] = o;     // in-place write h(l)
            // shift window; next w6 = h_old(l+4) = padded row l+7
            w0 = w1; w1 = w2; w2 = w3; w3 = w4; w4 = w5; w5 = w6;
            if (j + 1 < SEGL) {
                if (j < SEGL - 4)
                    w6 = *(float2*)&hS[(l + 7) * DC + dp];  // own-segment row, safe
                else if (j == SEGL - 4) w6 = t0;
                else if (j == SEGL - 3) w6 = t1;
                else                    w6 = t2;            // j == SEGL - 2
            }
        }
        __syncthreads();   // step-1 writes complete before step-2 reads
    }

    // ------- Step 2: NO smem writes; pool sum accumulated in registers -----
    float2 s = make_float2(0.f, 0.f);
    {
        float2 w0 = *(float2*)&hS[(ls + 0) * DC + dp];
        float2 w1 = *(float2*)&hS[(ls + 1) * DC + dp];
        float2 w2 = *(float2*)&hS[(ls + 2) * DC + dp];
        float2 w3 = *(float2*)&hS[(ls + 3) * DC + dp];
        float2 w4 = *(float2*)&hS[(ls + 4) * DC + dp];
        float2 w5 = *(float2*)&hS[(ls + 5) * DC + dp];
        float2 w6 = *(float2*)&hS[(ls + 6) * DC + dp];
        float4 wa = *(const float4*)&wS[ls * WP];
        float4 wb = *(const float4*)&wS[ls * WP + 4];

        #pragma unroll
        for (int j = 0; j < SEGL; j++) {
            int l = ls + j;
            float4 ca = wa, cb = wb;
            if (j + 1 < SEGL) {
                wa = *(const float4*)&wS[(l + 1) * WP];
                wb = *(const float4*)&wS[(l + 1) * WP + 4];
            }
            float mx = fmaxf(fmaxf(fmaxf(ca.x * w0.x, ca.y * w1.x),
                                   fmaxf(ca.z * w2.x, ca.w * w3.x)),
                             fmaxf(fmaxf(cb.x * w4.x, cb.y * w5.x), cb.z * w6.x));
            float my = fmaxf(fmaxf(fmaxf(ca.x * w0.y, ca.y * w1.y),
                                   fmaxf(ca.z * w2.y, ca.w * w3.y)),
                             fmaxf(fmaxf(cb.x * w4.y, cb.y * w5.y), cb.z * w6.y));
            s.x += fmaf(cb.w, w3.x - mx, mx);       // h2(l) accumulated directly
            s.y += fmaf(cb.w, w3.y - my, my);
            // shift window; reads are always safe (no writes this step)
            w0 = w1; w1 = w2; w2 = w3; w3 = w4; w4 = w5; w5 = w6;
            if (j + 1 < SEGL)
                w6 = *(float2*)&hS[(l + 7) * DC + dp];
        }
    }

    // partial sums via wS scratch (barrier first: others may still read wS)
    __syncthreads();
    *(float2*)&wS[seg * DC + dp] = s;    // NSEG*DC = 640 <= 2400
    __syncthreads();
    if (seg == 0 && dp < Dc) {
        float tx = 0.f, ty = 0.f;
        #pragma unroll
        for (int p = 0; p < NSEG; p++) {
            float2 v = *(float2*)&wS[p * DC + dp];
            tx += v.x; ty += v.y;
        }
        g_x[b * D_ + d0 + dp]     = fmaxf(tx, 0.f);
        g_x[b * D_ + d0 + dp + 1] = fmaxf(ty, 0.f);
    }
}

// ---------------------------------------------------------------------------
// Kernel 2: BN stats — one block per feature d, one thread per batch row.
// ---------------------------------------------------------------------------
__global__ void bn_kernel(const float* __restrict__ gamma,
                          const float* __restrict__ beta) {
    __shared__ float s1[4], s2[4];
    int d = blockIdx.x;
    int tid = threadIdx.x;              // 0..127 == batch row
    float v = g_x[tid * D_ + d];
    float a = v, q = v * v;
    #pragma unroll
    for (int o = 16; o > 0; o >>= 1) {
        a += __shfl_down_sync(0xffffffffu, a, o);
        q += __shfl_down_sync(0xffffffffu, q, o);
    }
    if ((tid & 31) == 0) { s1[tid >> 5] = a; s2[tid >> 5] = q; }
    __syncthreads();
    if (tid == 0) {
        float sum = s1[0] + s1[1] + s1[2] + s1[3];
        float sq  = s2[0] + s2[1] + s2[2] + s2[3];
        float mean = sum * (1.f / B_);
        float var  = sq * (1.f / B_) - mean * mean;
        float sc = gamma[d] * rsqrtf(var + 1e-5f);
        g_s[d] = sc;
        g_t[d] = beta[d] - mean * sc;
    }
}

// ---------------------------------------------------------------------------
// Kernel 3: sigmoid(x_norm @ W + b). One block per batch row; 432 threads =
// 54 outputs x 8 d-partitions; direct LDG of W (L2-resident), 8 independent
// accumulators (proven 6.85us — predicated form, faster than clamped).
// ---------------------------------------------------------------------------
__global__ void out_kernel(const float* __restrict__ W,
                           const float* __restrict__ bias,
                           float* __restrict__ out) {
    __shared__ float xs[D_];
    __shared__ float red[8][C_];
    int b = blockIdx.x;
    int tid = threadIdx.x;
    for (int dd = tid; dd < D_; dd += blockDim.x)
        xs[dd] = g_x[b * D_ + dd] * g_s[dd] + g_t[dd];
    __syncthreads();
    int c = tid % C_, part = tid / C_;  // part 0..7
    float acc[8] = {0.f, 0.f, 0.f, 0.f, 0.f, 0.f, 0.f, 0.f};
    #pragma unroll
    for (int j = 0; j < 38; j++) {
        int dd = part + 8 * j;
        if (dd < D_)
            acc[j & 7] = fmaf(xs[dd], __ldg(&W[dd * C_ + c]), acc[j & 7]);
    }
    red[part][c] = ((acc[0] + acc[1]) + (acc[2] + acc[3]))
                 + ((acc[4] + acc[5]) + (acc[6] + acc[7]));
    __syncthreads();
    if (part == 0) {
        float tot = bias[c];
        #pragma unroll
        for (int p = 0; p < 8; p++) tot += red[p][c];
        out[b * C_ + c] = 1.f / (1.f + expf(-tot));
    }
}

// ---------------------------------------------------------------------------
extern "C" void kernel_launch(void* const* d_in, const int* in_sizes, int n_in,
                              void* d_out, int out_size) {
    const float* node_embed   = (const float*)d_in[0];
    const float* node_eta     = (const float*)d_in[1];
    const float* edge_w       = (const float*)d_in[2];
    const float* bn_gamma     = (const float*)d_in[3];
    const float* bn_beta      = (const float*)d_in[4];
    const float* Wmat         = (const float*)d_in[5];
    const float* bias         = (const float*)d_in[6];
    const int*   docs         = (const int*)d_in[7];
    const int*   edges_matrix = (const int*)d_in[8];
    float* out = (float*)d_out;

    const int mpSmem = (HR * DC + L_ * WP) * (int)sizeof(float)
                     + L_ * (int)sizeof(int);   // 50,224 B
    cudaFuncSetAttribute(mp_kernel, cudaFuncAttributeMaxDynamicSharedMemorySize, mpSmem);

    edgew_kernel<<<(B_ * L_ * WP) / 512, 512>>>(docs, edges_matrix, edge_w, node_eta);

    dim3 grid(NCHUNK, B_);
    mp_kernel<<<grid, NTHR, mpSmem>>>(node_embed, docs);

    bn_kernel<<<D_, B_>>>(bn_gamma, bn_beta);

    out_kernel<<<B_, 8 * C_>>>(Wmat, bias, out);

    (void)in_sizes; (void)n_in; (void)out_size;
}